// round 15
// baseline (speedup 1.0000x reference)
#include <cuda_runtime.h>
#include <cstdint>

#define NN 8192
#define FF 8
#define TPB 224                     // 7 warps (gemv)
#define GRPW 8                      // rows per warp
#define RPB 56                      // rows per block
#define NB ((NN + RPB - 1) / RPB)   // 147 blocks (1/SM)
#define CH 128                      // j per chunk (lane owns 4 consecutive j)
#define NCH (NN / CH)               // 64 chunks
#define XTN 512                     // x nodes per tile (4 chunks)
#define NTILE (NN / XTN)            // 16 tiles
#define FTS 256                     // fid tile
#define FT (NN / FTS)               // 32
#define NPAIRS (FT * (FT + 1) / 2)  // 528 tile pairs
#define RT9 0.94868329805051381f    // sqrt(0.9)

typedef unsigned long long ull;

__device__ float g_dense[NN * FF];
__constant__ float c_w[785];        // MLP weights (copied D2D at launch)

// ---------------- f32x2 helpers ----------------
__device__ __forceinline__ ull fma2(ull a, ull b, ull c) {
    ull d; asm("fma.rn.f32x2 %0, %1, %2, %3;" : "=l"(d) : "l"(a), "l"(b), "l"(c)); return d;
}
__device__ __forceinline__ ull mul2(ull a, ull b) {
    ull d; asm("mul.rn.f32x2 %0, %1, %2;" : "=l"(d) : "l"(a), "l"(b)); return d;
}
__device__ __forceinline__ ull add2(ull a, ull b) {
    ull d; asm("add.rn.f32x2 %0, %1, %2;" : "=l"(d) : "l"(a), "l"(b)); return d;
}
__device__ __forceinline__ ull pack2(float lo, float hi) {
    ull d; asm("mov.b64 %0, {%1, %2};" : "=l"(d) : "f"(lo), "f"(hi)); return d;
}
__device__ __forceinline__ void unpack2(ull v, float& lo, float& hi) {
    asm("mov.b64 {%0, %1}, %2;" : "=f"(lo), "=f"(hi) : "l"(v));
}
__device__ __forceinline__ float ftanh(float x) {
    float t = fabsf(x);
    float e = __expf(-2.0f * t);
    float r = __fdividef(1.0f - e, 1.0f + e);
    return copysignf(r, x);
}
__device__ __forceinline__ float fsigmoid(float x) {
    float e = __expf(-fabsf(x));
    float p = __fdividef(1.0f, 1.0f + e);
    return (x >= 0.0f) ? p : 1.0f - p;
}

// =================================================================
// Kernel 1: g_dense = A @ X — EXACT R12 measured-best (57.9 us).
// Register double-buffered LDG.128 A stream, cp.async x tiles.
// =================================================================
__global__ void __launch_bounds__(TPB, 1)
gemv_kernel(const float* __restrict__ A, const float* __restrict__ X)
{
    __shared__ __align__(16) char sm[2 * 16384];

    const int tid  = threadIdx.x;
    const int lane = tid & 31;
    const int warp = tid >> 5;

    uint32_t smb;
    asm("{ .reg .u64 t; cvta.to.shared.u64 t, %1; cvt.u32.u64 %0, t; }"
        : "=r"(smb) : "l"(sm));

    const int i0w = blockIdx.x * RPB + warp * GRPW;
    const float* Ap[GRPW];
    #pragma unroll
    for (int r = 0; r < GRPW; r++) {
        int row = i0w + r; if (row > NN - 1) row = NN - 1;
        Ap[r] = A + (size_t)row * NN + lane * 4;
    }

    ull acc[GRPW][4];
    #pragma unroll
    for (int r = 0; r < GRPW; r++)
        #pragma unroll
        for (int kk = 0; kk < 4; kk++) acc[r][kk] = 0ull;

    float4 b0[GRPW], b1[GRPW];

    #define LDA(n, B)                                                          \
        do {                                                                   \
            const int n_ = (n) & (NCH - 1);                                    \
            _Pragma("unroll")                                                  \
            for (int r_ = 0; r_ < GRPW; r_++)                                  \
                (B)[r_] = __ldcs(reinterpret_cast<const float4*>(Ap[r_] + (size_t)n_ * CH)); \
        } while (0)

    #define STAGE(tt, bo)                                                      \
        do {                                                                   \
            for (int p_ = tid; p_ < XTN * 2; p_ += TPB) {                      \
                const int j_ = p_ >> 1, h_ = p_ & 1;                           \
                const float* src_ = X + ((size_t)(tt) * XTN + j_) * FF + h_ * 4; \
                const int c_ = j_ >> 7, l_ = (j_ >> 2) & 31, r_ = j_ & 3;      \
                const uint32_t dst_ = smb + (bo) + c_ * 4096                   \
                                    + (r_ * 2 + h_) * 512 + l_ * 16;           \
                asm volatile("cp.async.ca.shared.global [%0], [%1], 16;"       \
                             :: "r"(dst_), "l"(src_));                         \
            }                                                                  \
            asm volatile("cp.async.commit_group;" ::: "memory");               \
        } while (0)

    #define HALF(B, c0, c1, q0off)                                             \
        do {                                                                   \
            ull pa0_, pa1_, pb0_, pb1_, pc0_, pc1_, pd0_, pd1_;                \
            asm("ld.shared.v2.b64 {%0, %1}, [%2];" : "=l"(pa0_), "=l"(pa1_)    \
                : "r"(ba_ + (q0off)));                                         \
            asm("ld.shared.v2.b64 {%0, %1}, [%2];" : "=l"(pb0_), "=l"(pb1_)    \
                : "r"(ba_ + (q0off) + 512));                                   \
            asm("ld.shared.v2.b64 {%0, %1}, [%2];" : "=l"(pc0_), "=l"(pc1_)    \
                : "r"(ba_ + (q0off) + 1024));                                  \
            asm("ld.shared.v2.b64 {%0, %1}, [%2];" : "=l"(pd0_), "=l"(pd1_)    \
                : "r"(ba_ + (q0off) + 1536));                                  \
            _Pragma("unroll")                                                  \
            for (int r_ = 0; r_ < GRPW; r_++) {                                \
                ull w0_ = pack2((B)[r_].c0, (B)[r_].c0);                       \
                acc[r_][0] = fma2(w0_, pa0_, acc[r_][0]);                      \
                acc[r_][1] = fma2(w0_, pa1_, acc[r_][1]);                      \
                acc[r_][2] = fma2(w0_, pb0_, acc[r_][2]);                      \
                acc[r_][3] = fma2(w0_, pb1_, acc[r_][3]);                      \
                ull w1_ = pack2((B)[r_].c1, (B)[r_].c1);                       \
                acc[r_][0] = fma2(w1_, pc0_, acc[r_][0]);                      \
                acc[r_][1] = fma2(w1_, pc1_, acc[r_][1]);                      \
                acc[r_][2] = fma2(w1_, pd0_, acc[r_][2]);                      \
                acc[r_][3] = fma2(w1_, pd1_, acc[r_][3]);                      \
            }                                                                  \
        } while (0)

    #define COMPUTE(cbase, B)                                                  \
        do {                                                                   \
            const uint32_t ba_ = (cbase) + (uint32_t)lane * 16;                \
            HALF(B, x, y, 0);                                                  \
            HALF(B, z, w, 2048);                                               \
        } while (0)

    STAGE(0, 0);
    LDA(0, b0); LDA(1, b1);

    #pragma unroll 1
    for (int t = 0; t < NTILE; t++) {
        asm volatile("cp.async.wait_group 0;" ::: "memory");
        __syncthreads();
        if (t + 1 < NTILE) STAGE(t + 1, ((t + 1) & 1) * 16384);

        const uint32_t tb = smb + (uint32_t)(t & 1) * 16384;
        const int n = t * 4;
        COMPUTE(tb,          b0); LDA(n + 2, b0);
        COMPUTE(tb + 4096,   b1); LDA(n + 3, b1);
        COMPUTE(tb + 8192,   b0); LDA(n + 4, b0);
        COMPUTE(tb + 12288,  b1); LDA(n + 5, b1);
    }
    #undef LDA
    #undef STAGE
    #undef HALF
    #undef COMPUTE

    #pragma unroll
    for (int r = 0; r < GRPW; r++)
        #pragma unroll
        for (int kk = 0; kk < 4; kk++) {
            ull v = acc[r][kk];
            #pragma unroll
            for (int o = 16; o; o >>= 1)
                v = add2(v, __shfl_xor_sync(0xffffffffu, v, o));
            acc[r][kk] = v;
        }

    if (lane < GRPW && i0w + lane < NN) {
        float2* out = reinterpret_cast<float2*>(&g_dense[(size_t)(i0w + lane) * FF]);
        #pragma unroll
        for (int kk = 0; kk < 4; kk++) {
            float lo, hi;
            unpack2(acc[lane][kk], lo, hi);
            out[kk] = make_float2(lo, hi);
        }
    }
}

// =================================================================
// Kernel 2: sparse fidelity corrections — 4i x 2j register blocking
// with a BRANCHLESS screen: accumulate m = max |dot| over the 8
// cells (FMNMX), one compare per pass; rare hit path re-tests the
// retained dots. fid ⟺ |xn_i·xn_j| >= sqrt(0.9); hit -> weight
// becomes exactly 1: atomicAdd (1-A)*x both directions.
// =================================================================
__global__ void __launch_bounds__(128)
fid_kernel(const float* __restrict__ A, const float* __restrict__ X)
{
    // i-tile permuted (8 planes of 128 ull: node n -> g=n>>2, r=n&3,
    // piece k=r*2+h at ull idx g*2 + k*128); j-tile plain 32B/node
    __shared__ __align__(16) ull smi[1024];
    __shared__ __align__(16) ull smj[1024];

    const int tid = threadIdx.x;

    int p = blockIdx.x, ti = 0, rem = p;
    while (rem >= FT - ti) { rem -= FT - ti; ti++; }
    const int tj = ti + rem;

    // stage both tiles normalized (thread handles 2 nodes per side)
    for (int n = tid; n < FTS; n += 128) {
        {
            const float4* xp = reinterpret_cast<const float4*>(X + (size_t)(ti * FTS + n) * FF);
            float4 a = __ldg(xp), c = __ldg(xp + 1);
            float ss = a.x*a.x + a.y*a.y + a.z*a.z + a.w*a.w
                     + c.x*c.x + c.y*c.y + c.z*c.z + c.w*c.w;
            float inv = 1.0f / (sqrtf(ss) + 1e-12f);
            const int g = n >> 2, r = n & 3;
            smi[g*2 + (r*2+0)*128 + 0] = pack2(a.x*inv, a.y*inv);
            smi[g*2 + (r*2+0)*128 + 1] = pack2(a.z*inv, a.w*inv);
            smi[g*2 + (r*2+1)*128 + 0] = pack2(c.x*inv, c.y*inv);
            smi[g*2 + (r*2+1)*128 + 1] = pack2(c.z*inv, c.w*inv);
        }
        {
            const float4* xp = reinterpret_cast<const float4*>(X + (size_t)(tj * FTS + n) * FF);
            float4 a = __ldg(xp), c = __ldg(xp + 1);
            float ss = a.x*a.x + a.y*a.y + a.z*a.z + a.w*a.w
                     + c.x*c.x + c.y*c.y + c.z*c.z + c.w*c.w;
            float inv = 1.0f / (sqrtf(ss) + 1e-12f);
            smj[n*4 + 0] = pack2(a.x*inv, a.y*inv);
            smj[n*4 + 1] = pack2(a.z*inv, a.w*inv);
            smj[n*4 + 2] = pack2(c.x*inv, c.y*inv);
            smj[n*4 + 3] = pack2(c.z*inv, c.w*inv);
        }
    }
    __syncthreads();

    uint32_t sbi, sbj;
    asm("{ .reg .u64 t; cvta.to.shared.u64 t, %1; cvt.u32.u64 %0, t; }" : "=r"(sbi) : "l"(smi));
    asm("{ .reg .u64 t; cvta.to.shared.u64 t, %1; cvt.u32.u64 %0, t; }" : "=r"(sbj) : "l"(smj));

    // own 4 i-nodes into registers (group = tid&63, 16B lane stride)
    const int gi4 = tid & 63;
    ull xi[4][4];
    #pragma unroll
    for (int k = 0; k < 8; k++) {
        ull u0, u1;
        asm("ld.shared.v2.b64 {%0, %1}, [%2];" : "=l"(u0), "=l"(u1)
            : "r"(sbi + (uint32_t)gi4 * 16 + (uint32_t)k * 1024));
        xi[k >> 1][2 * (k & 1) + 0] = u0;
        xi[k >> 1][2 * (k & 1) + 1] = u1;
    }

    const int jslot = tid >> 6;    // 0..1, constant within warp half
    #pragma unroll 1
    for (int pass = 0; pass < 64; pass++) {
        const int jg = pass * 2 + jslot;   // 2-node j-group (0..127)
        // load 2 j nodes (4 LDS.128)
        ull xj0[4], xj1[4];
        asm("ld.shared.v2.b64 {%0, %1}, [%2];" : "=l"(xj0[0]), "=l"(xj0[1])
            : "r"(sbj + (uint32_t)jg * 64));
        asm("ld.shared.v2.b64 {%0, %1}, [%2];" : "=l"(xj0[2]), "=l"(xj0[3])
            : "r"(sbj + (uint32_t)jg * 64 + 16));
        asm("ld.shared.v2.b64 {%0, %1}, [%2];" : "=l"(xj1[0]), "=l"(xj1[1])
            : "r"(sbj + (uint32_t)jg * 64 + 32));
        asm("ld.shared.v2.b64 {%0, %1}, [%2];" : "=l"(xj1[2]), "=l"(xj1[3])
            : "r"(sbj + (uint32_t)jg * 64 + 48));

        float s[4][2];
        float m = 0.0f;
        #pragma unroll
        for (int r = 0; r < 4; r++) {
            ull d0 = mul2(xi[r][0], xj0[0]);
            d0 = fma2(xi[r][1], xj0[1], d0);
            d0 = fma2(xi[r][2], xj0[2], d0);
            d0 = fma2(xi[r][3], xj0[3], d0);
            ull d1 = mul2(xi[r][0], xj1[0]);
            d1 = fma2(xi[r][1], xj1[1], d1);
            d1 = fma2(xi[r][2], xj1[2], d1);
            d1 = fma2(xi[r][3], xj1[3], d1);
            float l0, h0, l1, h1;
            unpack2(d0, l0, h0);
            unpack2(d1, l1, h1);
            s[r][0] = l0 + h0;
            s[r][1] = l1 + h1;
            m = fmaxf(m, fabsf(s[r][0]));
            m = fmaxf(m, fabsf(s[r][1]));
        }

        if (m >= RT9) {                    // rare (~1e-3 of passes)
            #pragma unroll
            for (int r = 0; r < 4; r++)
                #pragma unroll
                for (int q = 0; q < 2; q++)
                    if (fabsf(s[r][q]) >= RT9) {
                        const int gi = ti * FTS + gi4 * 4 + r;
                        const int gj = tj * FTS + jg * 2 + q;
                        if (ti != tj || gj > gi) {
                            const float aij = __ldg(A + (size_t)gi * NN + gj);
                            const float aji = __ldg(A + (size_t)gj * NN + gi);
                            const float* xjv = X + (size_t)gj * FF;
                            const float* xiv = X + (size_t)gi * FF;
                            #pragma unroll
                            for (int f = 0; f < FF; f++)
                                atomicAdd(&g_dense[(size_t)gi * FF + f], (1.0f - aij) * __ldg(xjv + f));
                            #pragma unroll
                            for (int f = 0; f < FF; f++)
                                atomicAdd(&g_dense[(size_t)gj * FF + f], (1.0f - aji) * __ldg(xiv + f));
                        }
                    }
        }
    }
}

// =================================================================
// Kernel 3: per-row MLP + sigmoid head, weights in __constant__
// (no smem staging, no barrier), 64 blocks x 128 threads
// =================================================================
__global__ void __launch_bounds__(128)
mlp_kernel(float* __restrict__ out)
{
    const int i = blockIdx.x * 128 + threadIdx.x;

    float v[16], h[16];
    #pragma unroll
    for (int kk = 0; kk < 8; kk++) v[kk] = g_dense[(size_t)i * FF + kk];

    #define LAYER(IN, OUT, WOFF, BOFF, src, dst)                            \
        do {                                                                \
            _Pragma("unroll")                                               \
            for (int j_ = 0; j_ < (OUT); j_++) {                            \
                float s_ = c_w[(BOFF) + j_];                                \
                _Pragma("unroll")                                           \
                for (int k_ = 0; k_ < (IN); k_++)                           \
                    s_ = fmaf((src)[k_], c_w[(WOFF) + k_ * (OUT) + j_], s_);\
                (dst)[j_] = ftanh(s_);                                      \
            }                                                               \
        } while (0)

    LAYER(8, 16,   0, 128, v, h);
    LAYER(16, 16, 144, 400, h, v);
    LAYER(16, 12, 416, 608, v, h);
    LAYER(12, 8,  620, 716, h, v);
    LAYER(8, 4,   724, 756, v, h);
    LAYER(4, 4,   760, 776, h, v);
    #undef LAYER

    float z = c_w[784];
    #pragma unroll
    for (int kk = 0; kk < 4; kk++)
        z = fmaf(v[kk], c_w[780 + kk], z);
    out[i] = fsigmoid(z);
}

extern "C" void kernel_launch(void* const* d_in, const int* in_sizes, int n_in,
                              void* d_out, int out_size)
{
    const float* A = (const float*)d_in[0];
    const float* X = (const float*)d_in[1];

    // copy MLP weights into constant memory (D2D async, capture-legal)
    static const int offs[14] = {0, 128, 144, 400, 416, 608, 620, 716,
                                 724, 756, 760, 776, 780, 784};
    static const int cnts[14] = {128, 16, 256, 16, 192, 12, 96, 8,
                                 32, 4, 16, 4, 4, 1};
    for (int s = 0; s < 14; s++)
        cudaMemcpyToSymbolAsync(c_w, d_in[2 + s],
                                (size_t)cnts[s] * sizeof(float),
                                (size_t)offs[s] * sizeof(float),
                                cudaMemcpyDeviceToDevice, 0);

    gemv_kernel<<<NB, TPB>>>(A, X);       // direct stores: no memset
    fid_kernel<<<NPAIRS, 128>>>(A, X);    // atomic corrections on top
    mlp_kernel<<<NN / 128, 128>>>((float*)d_out);
}

// round 16
// speedup vs baseline: 1.1348x; 1.1348x over previous
#include <cuda_runtime.h>
#include <cstdint>

#define NN 8192
#define FF 8
#define TPB 224                     // 7 warps (gemv)
#define GRPW 8                      // rows per warp
#define RPB 56                      // rows per block
#define NB ((NN + RPB - 1) / RPB)   // 147 blocks (1/SM)
#define CH 128                      // j per chunk (lane owns 4 consecutive j)
#define NCH (NN / CH)               // 64 chunks
#define XTN 512                     // x nodes per tile (4 chunks)
#define NTILE (NN / XTN)            // 16 tiles
#define FTS 256                     // fid tile
#define FT (NN / FTS)               // 32
#define NPAIRS (FT * (FT + 1) / 2)  // 528 tile pairs
#define RT9 0.94868329805051381f    // sqrt(0.9)

typedef unsigned long long ull;

__device__ float g_dense[NN * FF];

// ---------------- f32x2 helpers ----------------
__device__ __forceinline__ ull fma2(ull a, ull b, ull c) {
    ull d; asm("fma.rn.f32x2 %0, %1, %2, %3;" : "=l"(d) : "l"(a), "l"(b), "l"(c)); return d;
}
__device__ __forceinline__ ull mul2(ull a, ull b) {
    ull d; asm("mul.rn.f32x2 %0, %1, %2;" : "=l"(d) : "l"(a), "l"(b)); return d;
}
__device__ __forceinline__ ull add2(ull a, ull b) {
    ull d; asm("add.rn.f32x2 %0, %1, %2;" : "=l"(d) : "l"(a), "l"(b)); return d;
}
__device__ __forceinline__ ull pack2(float lo, float hi) {
    ull d; asm("mov.b64 %0, {%1, %2};" : "=l"(d) : "f"(lo), "f"(hi)); return d;
}
__device__ __forceinline__ void unpack2(ull v, float& lo, float& hi) {
    asm("mov.b64 {%0, %1}, %2;" : "=f"(lo), "=f"(hi) : "l"(v));
}
__device__ __forceinline__ float ftanh(float x) {
    float t = fabsf(x);
    float e = __expf(-2.0f * t);
    float r = __fdividef(1.0f - e, 1.0f + e);
    return copysignf(r, x);
}
__device__ __forceinline__ float fsigmoid(float x) {
    float e = __expf(-fabsf(x));
    float p = __fdividef(1.0f, 1.0f + e);
    return (x >= 0.0f) ? p : 1.0f - p;
}

// =================================================================
// Kernel 1: g_dense += A @ X — R12 measured-best stream (57.9 us),
// final store switched to guarded atomicAdd so it can run
// concurrently with fid_kernel (both add into zeroed g_dense).
// =================================================================
__global__ void __launch_bounds__(TPB, 1)
gemv_kernel(const float* __restrict__ A, const float* __restrict__ X)
{
    __shared__ __align__(16) char sm[2 * 16384];

    const int tid  = threadIdx.x;
    const int lane = tid & 31;
    const int warp = tid >> 5;

    uint32_t smb;
    asm("{ .reg .u64 t; cvta.to.shared.u64 t, %1; cvt.u32.u64 %0, t; }"
        : "=r"(smb) : "l"(sm));

    const int i0w = blockIdx.x * RPB + warp * GRPW;
    const float* Ap[GRPW];
    #pragma unroll
    for (int r = 0; r < GRPW; r++) {
        int row = i0w + r; if (row > NN - 1) row = NN - 1;
        Ap[r] = A + (size_t)row * NN + lane * 4;
    }

    ull acc[GRPW][4];
    #pragma unroll
    for (int r = 0; r < GRPW; r++)
        #pragma unroll
        for (int kk = 0; kk < 4; kk++) acc[r][kk] = 0ull;

    float4 b0[GRPW], b1[GRPW];

    #define LDA(n, B)                                                          \
        do {                                                                   \
            const int n_ = (n) & (NCH - 1);                                    \
            _Pragma("unroll")                                                  \
            for (int r_ = 0; r_ < GRPW; r_++)                                  \
                (B)[r_] = __ldcs(reinterpret_cast<const float4*>(Ap[r_] + (size_t)n_ * CH)); \
        } while (0)

    #define STAGE(tt, bo)                                                      \
        do {                                                                   \
            for (int p_ = tid; p_ < XTN * 2; p_ += TPB) {                      \
                const int j_ = p_ >> 1, h_ = p_ & 1;                           \
                const float* src_ = X + ((size_t)(tt) * XTN + j_) * FF + h_ * 4; \
                const int c_ = j_ >> 7, l_ = (j_ >> 2) & 31, r_ = j_ & 3;      \
                const uint32_t dst_ = smb + (bo) + c_ * 4096                   \
                                    + (r_ * 2 + h_) * 512 + l_ * 16;           \
                asm volatile("cp.async.ca.shared.global [%0], [%1], 16;"       \
                             :: "r"(dst_), "l"(src_));                         \
            }                                                                  \
            asm volatile("cp.async.commit_group;" ::: "memory");               \
        } while (0)

    #define HALF(B, c0, c1, q0off)                                             \
        do {                                                                   \
            ull pa0_, pa1_, pb0_, pb1_, pc0_, pc1_, pd0_, pd1_;                \
            asm("ld.shared.v2.b64 {%0, %1}, [%2];" : "=l"(pa0_), "=l"(pa1_)    \
                : "r"(ba_ + (q0off)));                                         \
            asm("ld.shared.v2.b64 {%0, %1}, [%2];" : "=l"(pb0_), "=l"(pb1_)    \
                : "r"(ba_ + (q0off) + 512));                                   \
            asm("ld.shared.v2.b64 {%0, %1}, [%2];" : "=l"(pc0_), "=l"(pc1_)    \
                : "r"(ba_ + (q0off) + 1024));                                  \
            asm("ld.shared.v2.b64 {%0, %1}, [%2];" : "=l"(pd0_), "=l"(pd1_)    \
                : "r"(ba_ + (q0off) + 1536));                                  \
            _Pragma("unroll")                                                  \
            for (int r_ = 0; r_ < GRPW; r_++) {                                \
                ull w0_ = pack2((B)[r_].c0, (B)[r_].c0);                       \
                acc[r_][0] = fma2(w0_, pa0_, acc[r_][0]);                      \
                acc[r_][1] = fma2(w0_, pa1_, acc[r_][1]);                      \
                acc[r_][2] = fma2(w0_, pb0_, acc[r_][2]);                      \
                acc[r_][3] = fma2(w0_, pb1_, acc[r_][3]);                      \
                ull w1_ = pack2((B)[r_].c1, (B)[r_].c1);                       \
                acc[r_][0] = fma2(w1_, pc0_, acc[r_][0]);                      \
                acc[r_][1] = fma2(w1_, pc1_, acc[r_][1]);                      \
                acc[r_][2] = fma2(w1_, pd0_, acc[r_][2]);                      \
                acc[r_][3] = fma2(w1_, pd1_, acc[r_][3]);                      \
            }                                                                  \
        } while (0)

    #define COMPUTE(cbase, B)                                                  \
        do {                                                                   \
            const uint32_t ba_ = (cbase) + (uint32_t)lane * 16;                \
            HALF(B, x, y, 0);                                                  \
            HALF(B, z, w, 2048);                                               \
        } while (0)

    STAGE(0, 0);
    LDA(0, b0); LDA(1, b1);

    #pragma unroll 1
    for (int t = 0; t < NTILE; t++) {
        asm volatile("cp.async.wait_group 0;" ::: "memory");
        __syncthreads();
        if (t + 1 < NTILE) STAGE(t + 1, ((t + 1) & 1) * 16384);

        const uint32_t tb = smb + (uint32_t)(t & 1) * 16384;
        const int n = t * 4;
        COMPUTE(tb,          b0); LDA(n + 2, b0);
        COMPUTE(tb + 4096,   b1); LDA(n + 3, b1);
        COMPUTE(tb + 8192,   b0); LDA(n + 4, b0);
        COMPUTE(tb + 12288,  b1); LDA(n + 5, b1);
    }
    #undef LDA
    #undef STAGE
    #undef HALF
    #undef COMPUTE

    #pragma unroll
    for (int r = 0; r < GRPW; r++)
        #pragma unroll
        for (int kk = 0; kk < 4; kk++) {
            ull v = acc[r][kk];
            #pragma unroll
            for (int o = 16; o; o >>= 1)
                v = add2(v, __shfl_xor_sync(0xffffffffu, v, o));
            acc[r][kk] = v;
        }

    if (lane < GRPW && i0w + lane < NN) {   // exclusive rows; add into zeroed buf
        float* out = &g_dense[(size_t)(i0w + lane) * FF];
        #pragma unroll
        for (int kk = 0; kk < 4; kk++) {
            float lo, hi;
            unpack2(acc[lane][kk], lo, hi);
            atomicAdd(out + 2 * kk,     lo);
            atomicAdd(out + 2 * kk + 1, hi);
        }
    }
}

// =================================================================
// Kernel 2: sparse fidelity corrections — R14's measured 4x4
// register blocking, 128-thread blocks (3 CTAs/SM). Runs
// CONCURRENTLY with gemv on a forked stream (order-free: both
// atomicAdd into zeroed g_dense). fid ⟺ |xn_i·xn_j| >= sqrt(0.9);
// hit -> weight becomes exactly 1: atomicAdd (1-A)*x both ways.
// =================================================================
__global__ void __launch_bounds__(128)
fid_kernel(const float* __restrict__ A, const float* __restrict__ X)
{
    __shared__ __align__(16) ull smi[1024];
    __shared__ __align__(16) ull smj[1024];

    const int tid = threadIdx.x;

    int p = blockIdx.x, ti = 0, rem = p;
    while (rem >= FT - ti) { rem -= FT - ti; ti++; }
    const int tj = ti + rem;

    // stage both tiles normalized (thread handles 2 nodes per side)
    for (int n = tid; n < FTS; n += 128) {
        {
            const float4* xp = reinterpret_cast<const float4*>(X + (size_t)(ti * FTS + n) * FF);
            float4 a = __ldg(xp), c = __ldg(xp + 1);
            float ss = a.x*a.x + a.y*a.y + a.z*a.z + a.w*a.w
                     + c.x*c.x + c.y*c.y + c.z*c.z + c.w*c.w;
            float inv = 1.0f / (sqrtf(ss) + 1e-12f);
            const int g = n >> 2, r = n & 3;
            smi[g*2 + (r*2+0)*128 + 0] = pack2(a.x*inv, a.y*inv);
            smi[g*2 + (r*2+0)*128 + 1] = pack2(a.z*inv, a.w*inv);
            smi[g*2 + (r*2+1)*128 + 0] = pack2(c.x*inv, c.y*inv);
            smi[g*2 + (r*2+1)*128 + 1] = pack2(c.z*inv, c.w*inv);
        }
        {
            const float4* xp = reinterpret_cast<const float4*>(X + (size_t)(tj * FTS + n) * FF);
            float4 a = __ldg(xp), c = __ldg(xp + 1);
            float ss = a.x*a.x + a.y*a.y + a.z*a.z + a.w*a.w
                     + c.x*c.x + c.y*c.y + c.z*c.z + c.w*c.w;
            float inv = 1.0f / (sqrtf(ss) + 1e-12f);
            smj[n*4 + 0] = pack2(a.x*inv, a.y*inv);
            smj[n*4 + 1] = pack2(a.z*inv, a.w*inv);
            smj[n*4 + 2] = pack2(c.x*inv, c.y*inv);
            smj[n*4 + 3] = pack2(c.z*inv, c.w*inv);
        }
    }
    __syncthreads();

    uint32_t sbi, sbj;
    asm("{ .reg .u64 t; cvta.to.shared.u64 t, %1; cvt.u32.u64 %0, t; }" : "=r"(sbi) : "l"(smi));
    asm("{ .reg .u64 t; cvta.to.shared.u64 t, %1; cvt.u32.u64 %0, t; }" : "=r"(sbj) : "l"(smj));

    // own 4 i-nodes into registers (group = tid&63, 16B lane stride)
    const int gi4 = tid & 63;
    ull xi[4][4];
    #pragma unroll
    for (int k = 0; k < 8; k++) {
        ull u0, u1;
        asm("ld.shared.v2.b64 {%0, %1}, [%2];" : "=l"(u0), "=l"(u1)
            : "r"(sbi + (uint32_t)gi4 * 16 + (uint32_t)k * 1024));
        xi[k >> 1][2 * (k & 1) + 0] = u0;
        xi[k >> 1][2 * (k & 1) + 1] = u1;
    }

    const int jslot = tid >> 6;    // 0..1, constant within warp half
    #pragma unroll 1
    for (int pass = 0; pass < 32; pass++) {
        const int jg = pass * 2 + jslot;
        ull xj[4][4];
        #pragma unroll
        for (int r = 0; r < 4; r++) {
            ull u0, u1, u2, u3;
            asm("ld.shared.v2.b64 {%0, %1}, [%2];" : "=l"(u0), "=l"(u1)
                : "r"(sbj + (uint32_t)(jg * 4 + r) * 32));
            asm("ld.shared.v2.b64 {%0, %1}, [%2];" : "=l"(u2), "=l"(u3)
                : "r"(sbj + (uint32_t)(jg * 4 + r) * 32 + 16));
            xj[r][0] = u0; xj[r][1] = u1; xj[r][2] = u2; xj[r][3] = u3;
        }
        #pragma unroll
        for (int r = 0; r < 4; r++) {
            #pragma unroll
            for (int q = 0; q < 4; q++) {
                ull d = mul2(xi[r][0], xj[q][0]);
                d = fma2(xi[r][1], xj[q][1], d);
                d = fma2(xi[r][2], xj[q][2], d);
                d = fma2(xi[r][3], xj[q][3], d);
                float lo, hi; unpack2(d, lo, hi);
                const float s = lo + hi;
                if (fabsf(s) >= RT9) {          // rare (~1e-4)
                    const int gi = ti * FTS + gi4 * 4 + r;
                    const int gj = tj * FTS + jg * 4 + q;
                    if (ti != tj || gj > gi) {
                        const float aij = __ldg(A + (size_t)gi * NN + gj);
                        const float aji = __ldg(A + (size_t)gj * NN + gi);
                        const float* xjv = X + (size_t)gj * FF;
                        const float* xiv = X + (size_t)gi * FF;
                        #pragma unroll
                        for (int f = 0; f < FF; f++)
                            atomicAdd(&g_dense[(size_t)gi * FF + f], (1.0f - aij) * __ldg(xjv + f));
                        #pragma unroll
                        for (int f = 0; f < FF; f++)
                            atomicAdd(&g_dense[(size_t)gj * FF + f], (1.0f - aji) * __ldg(xiv + f));
                    }
                }
            }
        }
    }
}

// =================================================================
// Kernel 3: per-row MLP + sigmoid head (weights staged in smem)
// — measured-best 32 blocks x 256 threads version.
// =================================================================
#define NW_TOT 785
__global__ void __launch_bounds__(256)
mlp_kernel(const float* __restrict__ Wfm, const float* __restrict__ bfm,
           const float* __restrict__ Wc1, const float* __restrict__ bc1,
           const float* __restrict__ Wp1, const float* __restrict__ bp1,
           const float* __restrict__ Wc2, const float* __restrict__ bc2,
           const float* __restrict__ Wp2, const float* __restrict__ bp2,
           const float* __restrict__ Wc3, const float* __restrict__ bc3,
           const float* __restrict__ Wh,  const float* __restrict__ bh,
           float* __restrict__ out)
{
    __shared__ float w[NW_TOT];
    const int tid = threadIdx.x;

    struct Seg { const float* src; int off, n; };
    const Seg segs[14] = {
        {Wfm,   0, 128}, {bfm, 128, 16}, {Wc1, 144, 256}, {bc1, 400, 16},
        {Wp1, 416, 192}, {bp1, 608, 12}, {Wc2, 620,  96}, {bc2, 716,  8},
        {Wp2, 724,  32}, {bp2, 756,  4}, {Wc3, 760,  16}, {bc3, 776,  4},
        {Wh,  780,   4}, {bh,  784,  1}
    };
    #pragma unroll
    for (int s = 0; s < 14; s++)
        for (int kk = tid; kk < segs[s].n; kk += 256)
            w[segs[s].off + kk] = __ldg(segs[s].src + kk);
    __syncthreads();

    const int i = blockIdx.x * 256 + tid;

    float v[16], h[16];
    #pragma unroll
    for (int kk = 0; kk < 8; kk++) v[kk] = g_dense[(size_t)i * FF + kk];

    #define LAYER(IN, OUT, WOFF, BOFF, src, dst)                          \
        do {                                                              \
            _Pragma("unroll")                                             \
            for (int j_ = 0; j_ < (OUT); j_++) {                          \
                float s_ = w[(BOFF) + j_];                                \
                _Pragma("unroll")                                         \
                for (int k_ = 0; k_ < (IN); k_++)                         \
                    s_ = fmaf((src)[k_], w[(WOFF) + k_ * (OUT) + j_], s_);\
                (dst)[j_] = ftanh(s_);                                    \
            }                                                             \
        } while (0)

    LAYER(8, 16,   0, 128, v, h);
    LAYER(16, 16, 144, 400, h, v);
    LAYER(16, 12, 416, 608, v, h);
    LAYER(12, 8,  620, 716, h, v);
    LAYER(8, 4,   724, 756, v, h);
    LAYER(4, 4,   760, 776, h, v);
    #undef LAYER

    float z = w[784];
    #pragma unroll
    for (int kk = 0; kk < 4; kk++)
        z = fmaf(v[kk], w[780 + kk], z);
    out[i] = fsigmoid(z);
}

extern "C" void kernel_launch(void* const* d_in, const int* in_sizes, int n_in,
                              void* d_out, int out_size)
{
    const float* A = (const float*)d_in[0];
    const float* X = (const float*)d_in[1];

    // streams/events created once on the FIRST (uncaptured correctness)
    // call; the captured call records only the legal fork/join pattern.
    static cudaStream_t s1 = nullptr;
    static cudaEvent_t evFork = nullptr, evJoin = nullptr;
    if (s1 == nullptr) {
        cudaStreamCreateWithFlags(&s1, cudaStreamNonBlocking);
        cudaEventCreateWithFlags(&evFork, cudaEventDisableTiming);
        cudaEventCreateWithFlags(&evJoin, cudaEventDisableTiming);
    }

    void* gd = nullptr;
    cudaGetSymbolAddress(&gd, g_dense);
    cudaMemsetAsync(gd, 0, sizeof(float) * NN * FF, 0);

    // fork: fid runs concurrently with gemv (both atomicAdd, order-free)
    cudaEventRecord(evFork, 0);
    cudaStreamWaitEvent(s1, evFork, 0);

    gemv_kernel<<<NB, TPB, 0, 0>>>(A, X);
    fid_kernel<<<NPAIRS, 128, 0, s1>>>(A, X);

    cudaEventRecord(evJoin, s1);
    cudaStreamWaitEvent(0, evJoin, 0);

    mlp_kernel<<<NN / 256, 256, 0, 0>>>(
        (const float*)d_in[2],  (const float*)d_in[3],
        (const float*)d_in[4],  (const float*)d_in[5],
        (const float*)d_in[6],  (const float*)d_in[7],
        (const float*)d_in[8],  (const float*)d_in[9],
        (const float*)d_in[10], (const float*)d_in[11],
        (const float*)d_in[12], (const float*)d_in[13],
        (const float*)d_in[14], (const float*)d_in[15],
        (float*)d_out);
}

// round 17
// speedup vs baseline: 1.1528x; 1.0159x over previous
#include <cuda_runtime.h>
#include <cstdint>

#define NN 8192
#define FF 8
#define TPB 224                     // 7 warps (gemv)
#define GRPW 6                      // rows per warp (reduced: leave regfile room for fid co-residency)
#define RPB 42                      // rows per block
#define NB ((NN + RPB - 1) / RPB)   // 196 blocks
#define CH 128                      // j per chunk (lane owns 4 consecutive j)
#define NCH (NN / CH)               // 64 chunks
#define XTN 512                     // x nodes per tile (4 chunks)
#define NTILE (NN / XTN)            // 16 tiles
#define FTS 256                     // fid tile
#define FT (NN / FTS)               // 32
#define NPAIRS (FT * (FT + 1) / 2)  // 528 tile pairs
#define RT9 0.94868329805051381f    // sqrt(0.9)

typedef unsigned long long ull;

__device__ float g_dense[NN * FF];

// ---------------- f32x2 helpers ----------------
__device__ __forceinline__ ull fma2(ull a, ull b, ull c) {
    ull d; asm("fma.rn.f32x2 %0, %1, %2, %3;" : "=l"(d) : "l"(a), "l"(b), "l"(c)); return d;
}
__device__ __forceinline__ ull mul2(ull a, ull b) {
    ull d; asm("mul.rn.f32x2 %0, %1, %2;" : "=l"(d) : "l"(a), "l"(b)); return d;
}
__device__ __forceinline__ ull add2(ull a, ull b) {
    ull d; asm("add.rn.f32x2 %0, %1, %2;" : "=l"(d) : "l"(a), "l"(b)); return d;
}
__device__ __forceinline__ ull pack2(float lo, float hi) {
    ull d; asm("mov.b64 %0, {%1, %2};" : "=l"(d) : "f"(lo), "f"(hi)); return d;
}
__device__ __forceinline__ void unpack2(ull v, float& lo, float& hi) {
    asm("mov.b64 {%0, %1}, %2;" : "=f"(lo), "=f"(hi) : "l"(v));
}
__device__ __forceinline__ float ftanh(float x) {
    float t = fabsf(x);
    float e = __expf(-2.0f * t);
    float r = __fdividef(1.0f - e, 1.0f + e);
    return copysignf(r, x);
}
__device__ __forceinline__ float fsigmoid(float x) {
    float e = __expf(-fabsf(x));
    float p = __fdividef(1.0f, 1.0f + e);
    return (x >= 0.0f) ? p : 1.0f - p;
}

// =================================================================
// Kernel 1: g_dense += A @ X — R12-style stream at GRPW=6 so the
// register footprint (~45K/SM) leaves room for one co-resident
// fid block (19K). Final store is guarded atomicAdd into the
// zeroed buffer (order-free vs fid).
// =================================================================
__global__ void __launch_bounds__(TPB, 1)
gemv_kernel(const float* __restrict__ A, const float* __restrict__ X)
{
    __shared__ __align__(16) char sm[2 * 16384];

    const int tid  = threadIdx.x;
    const int lane = tid & 31;
    const int warp = tid >> 5;

    uint32_t smb;
    asm("{ .reg .u64 t; cvta.to.shared.u64 t, %1; cvt.u32.u64 %0, t; }"
        : "=r"(smb) : "l"(sm));

    const int i0w = blockIdx.x * RPB + warp * GRPW;
    const float* Ap[GRPW];
    #pragma unroll
    for (int r = 0; r < GRPW; r++) {
        int row = i0w + r; if (row > NN - 1) row = NN - 1;   // clamped reads
        Ap[r] = A + (size_t)row * NN + lane * 4;
    }

    ull acc[GRPW][4];
    #pragma unroll
    for (int r = 0; r < GRPW; r++)
        #pragma unroll
        for (int kk = 0; kk < 4; kk++) acc[r][kk] = 0ull;

    float4 b0[GRPW], b1[GRPW];

    #define LDA(n, B)                                                          \
        do {                                                                   \
            const int n_ = (n) & (NCH - 1);                                    \
            _Pragma("unroll")                                                  \
            for (int r_ = 0; r_ < GRPW; r_++)                                  \
                (B)[r_] = __ldcs(reinterpret_cast<const float4*>(Ap[r_] + (size_t)n_ * CH)); \
        } while (0)

    #define STAGE(tt, bo)                                                      \
        do {                                                                   \
            for (int p_ = tid; p_ < XTN * 2; p_ += TPB) {                      \
                const int j_ = p_ >> 1, h_ = p_ & 1;                           \
                const float* src_ = X + ((size_t)(tt) * XTN + j_) * FF + h_ * 4; \
                const int c_ = j_ >> 7, l_ = (j_ >> 2) & 31, r_ = j_ & 3;      \
                const uint32_t dst_ = smb + (bo) + c_ * 4096                   \
                                    + (r_ * 2 + h_) * 512 + l_ * 16;           \
                asm volatile("cp.async.ca.shared.global [%0], [%1], 16;"       \
                             :: "r"(dst_), "l"(src_));                         \
            }                                                                  \
            asm volatile("cp.async.commit_group;" ::: "memory");               \
        } while (0)

    #define HALF(B, c0, c1, q0off)                                             \
        do {                                                                   \
            ull pa0_, pa1_, pb0_, pb1_, pc0_, pc1_, pd0_, pd1_;                \
            asm("ld.shared.v2.b64 {%0, %1}, [%2];" : "=l"(pa0_), "=l"(pa1_)    \
                : "r"(ba_ + (q0off)));                                         \
            asm("ld.shared.v2.b64 {%0, %1}, [%2];" : "=l"(pb0_), "=l"(pb1_)    \
                : "r"(ba_ + (q0off) + 512));                                   \
            asm("ld.shared.v2.b64 {%0, %1}, [%2];" : "=l"(pc0_), "=l"(pc1_)    \
                : "r"(ba_ + (q0off) + 1024));                                  \
            asm("ld.shared.v2.b64 {%0, %1}, [%2];" : "=l"(pd0_), "=l"(pd1_)    \
                : "r"(ba_ + (q0off) + 1536));                                  \
            _Pragma("unroll")                                                  \
            for (int r_ = 0; r_ < GRPW; r_++) {                                \
                ull w0_ = pack2((B)[r_].c0, (B)[r_].c0);                       \
                acc[r_][0] = fma2(w0_, pa0_, acc[r_][0]);                      \
                acc[r_][1] = fma2(w0_, pa1_, acc[r_][1]);                      \
                acc[r_][2] = fma2(w0_, pb0_, acc[r_][2]);                      \
                acc[r_][3] = fma2(w0_, pb1_, acc[r_][3]);                      \
                ull w1_ = pack2((B)[r_].c1, (B)[r_].c1);                       \
                acc[r_][0] = fma2(w1_, pc0_, acc[r_][0]);                      \
                acc[r_][1] = fma2(w1_, pc1_, acc[r_][1]);                      \
                acc[r_][2] = fma2(w1_, pd0_, acc[r_][2]);                      \
                acc[r_][3] = fma2(w1_, pd1_, acc[r_][3]);                      \
            }                                                                  \
        } while (0)

    #define COMPUTE(cbase, B)                                                  \
        do {                                                                   \
            const uint32_t ba_ = (cbase) + (uint32_t)lane * 16;                \
            HALF(B, x, y, 0);                                                  \
            HALF(B, z, w, 2048);                                               \
        } while (0)

    STAGE(0, 0);
    LDA(0, b0); LDA(1, b1);

    #pragma unroll 1
    for (int t = 0; t < NTILE; t++) {
        asm volatile("cp.async.wait_group 0;" ::: "memory");
        __syncthreads();
        if (t + 1 < NTILE) STAGE(t + 1, ((t + 1) & 1) * 16384);

        const uint32_t tb = smb + (uint32_t)(t & 1) * 16384;
        const int n = t * 4;
        COMPUTE(tb,          b0); LDA(n + 2, b0);
        COMPUTE(tb + 4096,   b1); LDA(n + 3, b1);
        COMPUTE(tb + 8192,   b0); LDA(n + 4, b0);
        COMPUTE(tb + 12288,  b1); LDA(n + 5, b1);
    }
    #undef LDA
    #undef STAGE
    #undef HALF
    #undef COMPUTE

    #pragma unroll
    for (int r = 0; r < GRPW; r++)
        #pragma unroll
        for (int kk = 0; kk < 4; kk++) {
            ull v = acc[r][kk];
            #pragma unroll
            for (int o = 16; o; o >>= 1)
                v = add2(v, __shfl_xor_sync(0xffffffffu, v, o));
            acc[r][kk] = v;
        }

    if (lane < GRPW && i0w + lane < NN) {   // each row stored by exactly one warp
        float* out = &g_dense[(size_t)(i0w + lane) * FF];
        #pragma unroll
        for (int kk = 0; kk < 4; kk++) {
            float lo, hi;
            unpack2(acc[lane][kk], lo, hi);
            atomicAdd(out + 2 * kk,     lo);
            atomicAdd(out + 2 * kk + 1, hi);
        }
    }
}

// =================================================================
// Kernel 2: sparse fidelity corrections — R12's 4x4 register
// blocking, 128-thread blocks. Runs CONCURRENTLY with gemv on a
// forked stream; with gemv at ~45K regs, one fid block (19K)
// co-resides per SM and executes in gemv's idle issue slots.
// fid ⟺ |xn_i·xn_j| >= sqrt(0.9); hit -> weight exactly 1:
// atomicAdd (1-A)*x both directions into the zeroed buffer.
// =================================================================
__global__ void __launch_bounds__(128)
fid_kernel(const float* __restrict__ A, const float* __restrict__ X)
{
    __shared__ __align__(16) ull smi[1024];
    __shared__ __align__(16) ull smj[1024];

    const int tid = threadIdx.x;

    int p = blockIdx.x, ti = 0, rem = p;
    while (rem >= FT - ti) { rem -= FT - ti; ti++; }
    const int tj = ti + rem;

    // stage both tiles normalized (thread handles 2 nodes per side)
    for (int n = tid; n < FTS; n += 128) {
        {
            const float4* xp = reinterpret_cast<const float4*>(X + (size_t)(ti * FTS + n) * FF);
            float4 a = __ldg(xp), c = __ldg(xp + 1);
            float ss = a.x*a.x + a.y*a.y + a.z*a.z + a.w*a.w
                     + c.x*c.x + c.y*c.y + c.z*c.z + c.w*c.w;
            float inv = 1.0f / (sqrtf(ss) + 1e-12f);
            const int g = n >> 2, r = n & 3;
            smi[g*2 + (r*2+0)*128 + 0] = pack2(a.x*inv, a.y*inv);
            smi[g*2 + (r*2+0)*128 + 1] = pack2(a.z*inv, a.w*inv);
            smi[g*2 + (r*2+1)*128 + 0] = pack2(c.x*inv, c.y*inv);
            smi[g*2 + (r*2+1)*128 + 1] = pack2(c.z*inv, c.w*inv);
        }
        {
            const float4* xp = reinterpret_cast<const float4*>(X + (size_t)(tj * FTS + n) * FF);
            float4 a = __ldg(xp), c = __ldg(xp + 1);
            float ss = a.x*a.x + a.y*a.y + a.z*a.z + a.w*a.w
                     + c.x*c.x + c.y*c.y + c.z*c.z + c.w*c.w;
            float inv = 1.0f / (sqrtf(ss) + 1e-12f);
            smj[n*4 + 0] = pack2(a.x*inv, a.y*inv);
            smj[n*4 + 1] = pack2(a.z*inv, a.w*inv);
            smj[n*4 + 2] = pack2(c.x*inv, c.y*inv);
            smj[n*4 + 3] = pack2(c.z*inv, c.w*inv);
        }
    }
    __syncthreads();

    uint32_t sbi, sbj;
    asm("{ .reg .u64 t; cvta.to.shared.u64 t, %1; cvt.u32.u64 %0, t; }" : "=r"(sbi) : "l"(smi));
    asm("{ .reg .u64 t; cvta.to.shared.u64 t, %1; cvt.u32.u64 %0, t; }" : "=r"(sbj) : "l"(smj));

    // own 4 i-nodes into registers (group = tid&63, 16B lane stride)
    const int gi4 = tid & 63;
    ull xi[4][4];
    #pragma unroll
    for (int k = 0; k < 8; k++) {
        ull u0, u1;
        asm("ld.shared.v2.b64 {%0, %1}, [%2];" : "=l"(u0), "=l"(u1)
            : "r"(sbi + (uint32_t)gi4 * 16 + (uint32_t)k * 1024));
        xi[k >> 1][2 * (k & 1) + 0] = u0;
        xi[k >> 1][2 * (k & 1) + 1] = u1;
    }

    const int jslot = tid >> 6;    // 0..1, constant within warp half
    #pragma unroll 1
    for (int pass = 0; pass < 32; pass++) {
        const int jg = pass * 2 + jslot;
        ull xj[4][4];
        #pragma unroll
        for (int r = 0; r < 4; r++) {
            ull u0, u1, u2, u3;
            asm("ld.shared.v2.b64 {%0, %1}, [%2];" : "=l"(u0), "=l"(u1)
                : "r"(sbj + (uint32_t)(jg * 4 + r) * 32));
            asm("ld.shared.v2.b64 {%0, %1}, [%2];" : "=l"(u2), "=l"(u3)
                : "r"(sbj + (uint32_t)(jg * 4 + r) * 32 + 16));
            xj[r][0] = u0; xj[r][1] = u1; xj[r][2] = u2; xj[r][3] = u3;
        }
        #pragma unroll
        for (int r = 0; r < 4; r++) {
            #pragma unroll
            for (int q = 0; q < 4; q++) {
                ull d = mul2(xi[r][0], xj[q][0]);
                d = fma2(xi[r][1], xj[q][1], d);
                d = fma2(xi[r][2], xj[q][2], d);
                d = fma2(xi[r][3], xj[q][3], d);
                float lo, hi; unpack2(d, lo, hi);
                const float s = lo + hi;
                if (fabsf(s) >= RT9) {          // rare (~1e-4)
                    const int gi = ti * FTS + gi4 * 4 + r;
                    const int gj = tj * FTS + jg * 4 + q;
                    if (ti != tj || gj > gi) {
                        const float aij = __ldg(A + (size_t)gi * NN + gj);
                        const float aji = __ldg(A + (size_t)gj * NN + gi);
                        const float* xjv = X + (size_t)gj * FF;
                        const float* xiv = X + (size_t)gi * FF;
                        #pragma unroll
                        for (int f = 0; f < FF; f++)
                            atomicAdd(&g_dense[(size_t)gi * FF + f], (1.0f - aij) * __ldg(xjv + f));
                        #pragma unroll
                        for (int f = 0; f < FF; f++)
                            atomicAdd(&g_dense[(size_t)gj * FF + f], (1.0f - aji) * __ldg(xiv + f));
                    }
                }
            }
        }
    }
}

// =================================================================
// Kernel 3: per-row MLP + sigmoid head (weights staged in smem)
// =================================================================
#define NW_TOT 785
__global__ void __launch_bounds__(256)
mlp_kernel(const float* __restrict__ Wfm, const float* __restrict__ bfm,
           const float* __restrict__ Wc1, const float* __restrict__ bc1,
           const float* __restrict__ Wp1, const float* __restrict__ bp1,
           const float* __restrict__ Wc2, const float* __restrict__ bc2,
           const float* __restrict__ Wp2, const float* __restrict__ bp2,
           const float* __restrict__ Wc3, const float* __restrict__ bc3,
           const float* __restrict__ Wh,  const float* __restrict__ bh,
           float* __restrict__ out)
{
    __shared__ float w[NW_TOT];
    const int tid = threadIdx.x;

    struct Seg { const float* src; int off, n; };
    const Seg segs[14] = {
        {Wfm,   0, 128}, {bfm, 128, 16}, {Wc1, 144, 256}, {bc1, 400, 16},
        {Wp1, 416, 192}, {bp1, 608, 12}, {Wc2, 620,  96}, {bc2, 716,  8},
        {Wp2, 724,  32}, {bp2, 756,  4}, {Wc3, 760,  16}, {bc3, 776,  4},
        {Wh,  780,   4}, {bh,  784,  1}
    };
    #pragma unroll
    for (int s = 0; s < 14; s++)
        for (int kk = tid; kk < segs[s].n; kk += 256)
            w[segs[s].off + kk] = __ldg(segs[s].src + kk);
    __syncthreads();

    const int i = blockIdx.x * 256 + tid;

    float v[16], h[16];
    #pragma unroll
    for (int kk = 0; kk < 8; kk++) v[kk] = g_dense[(size_t)i * FF + kk];

    #define LAYER(IN, OUT, WOFF, BOFF, src, dst)                          \
        do {                                                              \
            _Pragma("unroll")                                             \
            for (int j_ = 0; j_ < (OUT); j_++) {                          \
                float s_ = w[(BOFF) + j_];                                \
                _Pragma("unroll")                                         \
                for (int k_ = 0; k_ < (IN); k_++)                         \
                    s_ = fmaf((src)[k_], w[(WOFF) + k_ * (OUT) + j_], s_);\
                (dst)[j_] = ftanh(s_);                                    \
            }                                                             \
        } while (0)

    LAYER(8, 16,   0, 128, v, h);
    LAYER(16, 16, 144, 400, h, v);
    LAYER(16, 12, 416, 608, v, h);
    LAYER(12, 8,  620, 716, h, v);
    LAYER(8, 4,   724, 756, v, h);
    LAYER(4, 4,   760, 776, h, v);
    #undef LAYER

    float z = w[784];
    #pragma unroll
    for (int kk = 0; kk < 4; kk++)
        z = fmaf(v[kk], w[780 + kk], z);
    out[i] = fsigmoid(z);
}

extern "C" void kernel_launch(void* const* d_in, const int* in_sizes, int n_in,
                              void* d_out, int out_size)
{
    const float* A = (const float*)d_in[0];
    const float* X = (const float*)d_in[1];

    // streams/events created once on the FIRST (uncaptured correctness)
    // call; the captured call records only the legal fork/join pattern.
    static cudaStream_t s1 = nullptr;
    static cudaEvent_t evFork = nullptr, evJoin = nullptr;
    if (s1 == nullptr) {
        cudaStreamCreateWithFlags(&s1, cudaStreamNonBlocking);
        cudaEventCreateWithFlags(&evFork, cudaEventDisableTiming);
        cudaEventCreateWithFlags(&evJoin, cudaEventDisableTiming);
    }

    void* gd = nullptr;
    cudaGetSymbolAddress(&gd, g_dense);
    cudaMemsetAsync(gd, 0, sizeof(float) * NN * FF, 0);

    // fork: fid runs concurrently with gemv (both atomicAdd, order-free)
    cudaEventRecord(evFork, 0);
    cudaStreamWaitEvent(s1, evFork, 0);

    gemv_kernel<<<NB, TPB, 0, 0>>>(A, X);
    fid_kernel<<<NPAIRS, 128, 0, s1>>>(A, X);

    cudaEventRecord(evJoin, s1);
    cudaStreamWaitEvent(0, evJoin, 0);

    mlp_kernel<<<NN / 256, 256, 0, 0>>>(
        (const float*)d_in[2],  (const float*)d_in[3],
        (const float*)d_in[4],  (const float*)d_in[5],
        (const float*)d_in[6],  (const float*)d_in[7],
        (const float*)d_in[8],  (const float*)d_in[9],
        (const float*)d_in[10], (const float*)d_in[11],
        (const float*)d_in[12], (const float*)d_in[13],
        (const float*)d_in[14], (const float*)d_in[15],
        (float*)d_out);
}